// round 14
// baseline (speedup 1.0000x reference)
#include <cuda_runtime.h>
#include <cuda_fp16.h>
#include <stdint.h>

// ---------------- problem constants ----------------
#define N_USERS  50000
#define N_ITEMS  100000
#define N_NODES  (N_USERS + N_ITEMS)     // 150000
#define N_EDGES  2400000
#define DIM      64
#define BATCH    4096

#define TOTAL    (N_NODES * DIM)         // 9,600,000 floats
#define TOT8     (TOTAL / 8)             // uint4-of-half count per buffer

#define SCAN_B   1024
#define NBLK     ((N_NODES + SCAN_B - 1) / SCAN_B)   // 147

#define FLG_AGG  (1ULL << 62)
#define FLG_INC  (2ULL << 62)

#define T           256
#define HIST_BLOCKS (((N_EDGES / 4) + T - 1) / T)      // 2344
#define SCT_BLOCKS  HIST_BLOCKS
#define CVT_BLOCKS  ((TOT8 + T - 1) / T)               // 4688

// ---------------- scratch (device globals; zero-initialized at load) ----------------
// TWO state buffers (fp16): bufA = emb -> layer-2 output; bufB = layer-1 output.
__device__ uint4 g_bufA[TOT8];
__device__ uint4 g_bufB[TOT8];

// edge record: .x = src * 8 (uint4-row base index), .y = val as duplicated half2
__device__ int2  g_edge  [N_EDGES];
__device__ int   g_cnt   [N_NODES];      // degree counter; countdown scatter returns it to 0
__device__ int   g_rowptr[N_NODES + 1];
__device__ unsigned long long g_part[NBLK];   // lookback scan state (reset every run)

// ---------------- helpers ----------------
__device__ __forceinline__ unsigned pack_h2(float a, float b) {
    __half2 h = __floats2half2_rn(a, b);
    return *reinterpret_cast<unsigned*>(&h);
}
__device__ __forceinline__ float2 unpack_h2(unsigned u) {
    return __half22float2(*reinterpret_cast<__half2*>(&u));
}
__device__ __forceinline__ unsigned f32_to_h2(float f) {
    __half2 h = __float2half2_rn(f);
    return *reinterpret_cast<unsigned*>(&h);
}
__device__ __forceinline__ void hfma2_asm(unsigned& acc, unsigned v, unsigned h) {
    asm("fma.rn.f16x2 %0, %1, %2, %0;" : "+r"(acc) : "r"(v), "r"(h));
}

// ---------------- launch 1: histogram (+ g_part reset) ----------------------------
__global__ void hist_kernel(const int* __restrict__ dst) {
    int t = blockIdx.x * blockDim.x + threadIdx.x;
    if (t < NBLK) g_part[t] = 0ULL;                  // reset lookback state
    if (t * 4 >= N_EDGES) return;
    int4 d = reinterpret_cast<const int4*>(dst)[t];
    atomicAdd(&g_cnt[d.x], 1);
    atomicAdd(&g_cnt[d.y], 1);
    atomicAdd(&g_cnt[d.z], 1);
    atomicAdd(&g_cnt[d.w], 1);
}

// ---------------- launch 2: one-pass decoupled-lookback exclusive scan ------------
__global__ void scan_kernel() {
    __shared__ int warp_tot[32];
    __shared__ int s_prefix;
    __shared__ int s_total;
    int b    = blockIdx.x;
    int gid  = b * SCAN_B + threadIdx.x;
    int lane = threadIdx.x & 31;
    int wid  = threadIdx.x >> 5;

    int v = (gid < N_NODES) ? g_cnt[gid] : 0;
    int inc = v;
    #pragma unroll
    for (int off = 1; off < 32; off <<= 1) {
        int t = __shfl_up_sync(0xFFFFFFFFu, inc, off);
        if (lane >= off) inc += t;
    }
    if (lane == 31) warp_tot[wid] = inc;
    __syncthreads();
    if (wid == 0) {
        int t = warp_tot[lane];
        int s = t;
        #pragma unroll
        for (int off = 1; off < 32; off <<= 1) {
            int u = __shfl_up_sync(0xFFFFFFFFu, s, off);
            if (lane >= off) s += u;
        }
        warp_tot[lane] = s - t;
    }
    __syncthreads();
    int ex = inc - v + warp_tot[wid];                   // exclusive within block
    if (threadIdx.x == SCAN_B - 1) s_total = ex + v;
    __syncthreads();
    int total = s_total;

    if (threadIdx.x == 0) {
        if (b == 0) {
            atomicExch(&g_part[0], FLG_INC | (unsigned long long)(unsigned)total);
            s_prefix = 0;
        } else {
            atomicExch(&g_part[b], FLG_AGG | (unsigned long long)(unsigned)total);
            int run = 0;
            int p = b - 1;
            while (true) {
                unsigned long long st  = atomicAdd(&g_part[p], 0ULL);
                unsigned long long flg = st & (3ULL << 62);
                if (flg == FLG_INC) { run += (int)(unsigned)st; break; }
                if (flg == FLG_AGG) { run += (int)(unsigned)st; p--; }
            }
            atomicExch(&g_part[b],
                       FLG_INC | (unsigned long long)(unsigned)(run + total));
            s_prefix = run;
        }
    }
    __syncthreads();
    if (gid < N_NODES) g_rowptr[gid] = ex + s_prefix;
    if (b == NBLK - 1 && threadIdx.x == 0) g_rowptr[N_NODES] = N_EDGES;
}

// ---------------- launch 3: scatter ∥ convert (disjoint block ranges) -------------
// scatter pre-packs the edge record: src*8 (uint4-row base) + val as dup half2.
__global__ void sct_cvt_kernel(const int* __restrict__ src,
                               const int* __restrict__ dst,
                               const float* __restrict__ vals,
                               const float* __restrict__ eu,
                               const float* __restrict__ ei) {
    if (blockIdx.x < SCT_BLOCKS) {
        int t = blockIdx.x * T + threadIdx.x;
        if (t * 4 >= N_EDGES) return;
        int4   s4 = reinterpret_cast<const int4*>(src)[t];
        int4   d4 = reinterpret_cast<const int4*>(dst)[t];
        float4 v4 = reinterpret_cast<const float4*>(vals)[t];
        int p;
        p = g_rowptr[d4.x] + atomicSub(&g_cnt[d4.x], 1) - 1;
        g_edge[p] = make_int2(s4.x * 8, (int)f32_to_h2(v4.x));
        p = g_rowptr[d4.y] + atomicSub(&g_cnt[d4.y], 1) - 1;
        g_edge[p] = make_int2(s4.y * 8, (int)f32_to_h2(v4.y));
        p = g_rowptr[d4.z] + atomicSub(&g_cnt[d4.z], 1) - 1;
        g_edge[p] = make_int2(s4.z * 8, (int)f32_to_h2(v4.z));
        p = g_rowptr[d4.w] + atomicSub(&g_cnt[d4.w], 1) - 1;
        g_edge[p] = make_int2(s4.w * 8, (int)f32_to_h2(v4.w));
    } else {
        int idx = (blockIdx.x - SCT_BLOCKS) * T + threadIdx.x;   // uint4 index
        if (idx >= TOT8) return;
        const int nu8 = (N_USERS * DIM) / 8;
        const float4* s;
        if (idx < nu8) s = reinterpret_cast<const float4*>(eu) + (size_t)idx * 2;
        else           s = reinterpret_cast<const float4*>(ei) + (size_t)(idx - nu8) * 2;
        float4 a = s[0], b = s[1];
        uint4 o;
        o.x = pack_h2(a.x, a.y);
        o.y = pack_h2(a.z, a.w);
        o.z = pack_h2(b.x, b.y);
        o.w = pack_h2(b.z, b.w);
        g_bufA[idx] = o;
    }
}

// ---------------- launches 4,5: gather SpMM (asm HFMA2, pre-packed edges) --------
// one warp per dst node; c = lane&7 -> 16B chunk of row; slot = lane>>3 in [0,4)
// -> edge stream. Edge record already holds src*8 and val as dup half2: no
// per-edge convert or scale in the hot loop.
__global__ void __launch_bounds__(256, 8) spmm_half_kernel(
        const uint4* __restrict__ x, uint4* __restrict__ y) {
    int node = blockIdx.x * (blockDim.x >> 5) + (threadIdx.x >> 5);
    if (node >= N_NODES) return;
    int lane = threadIdx.x & 31;
    int c    = lane & 7;
    int slot = lane >> 3;

    int beg = g_rowptr[node];
    int end = g_rowptr[node + 1];

    unsigned acc0 = 0u, acc1 = 0u, acc2 = 0u, acc3 = 0u;   // half2 +0.0 pairs

    int j = beg + slot;
    for (; j + 4 < end; j += 8) {
        int2  e0 = g_edge[j];
        int2  e1 = g_edge[j + 4];
        uint4 h0 = x[e0.x + c];
        uint4 h1 = x[e1.x + c];
        unsigned v0 = (unsigned)e0.y;
        unsigned v1 = (unsigned)e1.y;
        hfma2_asm(acc0, v0, h0.x);
        hfma2_asm(acc1, v0, h0.y);
        hfma2_asm(acc2, v0, h0.z);
        hfma2_asm(acc3, v0, h0.w);
        hfma2_asm(acc0, v1, h1.x);
        hfma2_asm(acc1, v1, h1.y);
        hfma2_asm(acc2, v1, h1.z);
        hfma2_asm(acc3, v1, h1.w);
    }
    if (j < end) {
        int2  e0 = g_edge[j];
        uint4 h0 = x[e0.x + c];
        unsigned v0 = (unsigned)e0.y;
        hfma2_asm(acc0, v0, h0.x);
        hfma2_asm(acc1, v0, h0.y);
        hfma2_asm(acc2, v0, h0.z);
        hfma2_asm(acc3, v0, h0.w);
    }

    // convert to fp32 and combine the 4 slot groups in fp32
    float a[8];
    { float2 f = unpack_h2(acc0); a[0] = f.x; a[1] = f.y; }
    { float2 f = unpack_h2(acc1); a[2] = f.x; a[3] = f.y; }
    { float2 f = unpack_h2(acc2); a[4] = f.x; a[5] = f.y; }
    { float2 f = unpack_h2(acc3); a[6] = f.x; a[7] = f.y; }
    #pragma unroll
    for (int k = 0; k < 8; k++) {
        a[k] += __shfl_xor_sync(0xFFFFFFFFu, a[k], 8);
        a[k] += __shfl_xor_sync(0xFFFFFFFFu, a[k], 16);
    }
    if (slot == 0) {
        uint4 o;
        o.x = pack_h2(a[0], a[1]);
        o.y = pack_h2(a[2], a[3]);
        o.z = pack_h2(a[4], a[5]);
        o.w = pack_h2(a[6], a[7]);
        y[node * 8 + c] = o;
    }
}

// ---------------- launch 6: fused layer-3 gather + dot (fp32 accumulate) ---------
__device__ __forceinline__ void gather3_chunk(const uint4* __restrict__ x2,
                                              int node, int c, int slot,
                                              float (&g)[8]) {
    int beg = g_rowptr[node];
    int end = g_rowptr[node + 1];
    #pragma unroll
    for (int k = 0; k < 8; k++) g[k] = 0.f;
    for (int j = beg + slot; j < end; j += 4) {
        int2  ed = g_edge[j];
        // low half of the dup half2 -> fp32
        float v = __low2float(*reinterpret_cast<__half2*>(&ed.y));
        uint4 h = x2[ed.x + c];
        float2 f;
        f = unpack_h2(h.x); g[0] += v * f.x; g[1] += v * f.y;
        f = unpack_h2(h.y); g[2] += v * f.x; g[3] += v * f.y;
        f = unpack_h2(h.z); g[4] += v * f.x; g[5] += v * f.y;
        f = unpack_h2(h.w); g[6] += v * f.x; g[7] += v * f.y;
    }
    #pragma unroll
    for (int k = 0; k < 8; k++) {
        g[k] += __shfl_xor_sync(0xFFFFFFFFu, g[k], 8);
        g[k] += __shfl_xor_sync(0xFFFFFFFFu, g[k], 16);
    }
}

// x1 = g_bufB (layer-1 output), x2 = g_bufA (layer-2 output)
__global__ void dot_fused_kernel(const int* __restrict__ users,
                                 const int* __restrict__ items,
                                 const float* __restrict__ eu,
                                 const float* __restrict__ ei,
                                 float* __restrict__ out) {
    int b = blockIdx.x * (blockDim.x >> 5) + (threadIdx.x >> 5);
    if (b >= BATCH) return;
    int lane = threadIdx.x & 31;
    int c    = lane & 7;
    int slot = lane >> 3;

    int u  = users[b];
    int im = items[b];
    int ni = N_USERS + im;

    float gu[8], gi[8];
    gather3_chunk(g_bufA, u,  c, slot, gu);
    gather3_chunk(g_bufA, ni, c, slot, gi);

    const float4* pu4 = reinterpret_cast<const float4*>(eu + u  * DIM + c * 8);
    const float4* pi4 = reinterpret_cast<const float4*>(ei + im * DIM + c * 8);
    float4 bu0 = pu4[0], bu1 = pu4[1];
    float4 bi0 = pi4[0], bi1 = pi4[1];

    uint4 u1h = g_bufB[u  * 8 + c], u2h = g_bufA[u  * 8 + c];
    uint4 i1h = g_bufB[ni * 8 + c], i2h = g_bufA[ni * 8 + c];

    float ru[8], ri[8];
    {
        float2 t;
        t = unpack_h2(u1h.x); ru[0] = bu0.x + t.x; ru[1] = bu0.y + t.y;
        t = unpack_h2(u1h.y); ru[2] = bu0.z + t.x; ru[3] = bu0.w + t.y;
        t = unpack_h2(u1h.z); ru[4] = bu1.x + t.x; ru[5] = bu1.y + t.y;
        t = unpack_h2(u1h.w); ru[6] = bu1.z + t.x; ru[7] = bu1.w + t.y;
        t = unpack_h2(u2h.x); ru[0] += t.x; ru[1] += t.y;
        t = unpack_h2(u2h.y); ru[2] += t.x; ru[3] += t.y;
        t = unpack_h2(u2h.z); ru[4] += t.x; ru[5] += t.y;
        t = unpack_h2(u2h.w); ru[6] += t.x; ru[7] += t.y;

        t = unpack_h2(i1h.x); ri[0] = bi0.x + t.x; ri[1] = bi0.y + t.y;
        t = unpack_h2(i1h.y); ri[2] = bi0.z + t.x; ri[3] = bi0.w + t.y;
        t = unpack_h2(i1h.z); ri[4] = bi1.x + t.x; ri[5] = bi1.y + t.y;
        t = unpack_h2(i1h.w); ri[6] = bi1.z + t.x; ri[7] = bi1.w + t.y;
        t = unpack_h2(i2h.x); ri[0] += t.x; ri[1] += t.y;
        t = unpack_h2(i2h.y); ri[2] += t.x; ri[3] += t.y;
        t = unpack_h2(i2h.z); ri[4] += t.x; ri[5] += t.y;
        t = unpack_h2(i2h.w); ri[6] += t.x; ri[7] += t.y;
    }

    float p = 0.f;
    #pragma unroll
    for (int k = 0; k < 8; k++)
        p += (ru[k] + gu[k]) * (ri[k] + gi[k]);

    p += __shfl_xor_sync(0xFFFFFFFFu, p, 1);
    p += __shfl_xor_sync(0xFFFFFFFFu, p, 2);
    p += __shfl_xor_sync(0xFFFFFFFFu, p, 4);

    if (lane == 0)
        out[b] = p * (1.0f / 16.0f);     // (1/4)^2 mean-pool factors
}

// ---------------- launch ----------------
extern "C" void kernel_launch(void* const* d_in, const int* in_sizes, int n_in,
                              void* d_out, int out_size) {
    (void)in_sizes; (void)n_in; (void)out_size;
    const float* emb_user = (const float*)d_in[0];
    const float* emb_item = (const float*)d_in[1];
    const float* vals     = (const float*)d_in[2];
    const int*   src      = (const int*)  d_in[3];
    const int*   dst      = (const int*)  d_in[4];
    const int*   users    = (const int*)  d_in[5];
    const int*   items    = (const int*)  d_in[6];
    float* out = (float*)d_out;

    uint4 *bA, *bB;
    cudaGetSymbolAddress((void**)&bA, g_bufA);
    cudaGetSymbolAddress((void**)&bB, g_bufB);

    // 1: histogram (+ g_part reset)
    hist_kernel<<<HIST_BLOCKS, T>>>(dst);
    // 2: one-pass scan -> rowptr
    scan_kernel<<<NBLK, SCAN_B>>>();
    // 3: scatter ∥ convert (scatter leaves g_cnt zeroed for next replay)
    sct_cvt_kernel<<<SCT_BLOCKS + CVT_BLOCKS, T>>>(src, dst, vals,
                                                   emb_user, emb_item);

    // 4,5: propagation (fp16 state, asm HFMA2, pre-packed edges)
    const int wpb = T / 32;
    const int grid_spmm = (N_NODES + wpb - 1) / wpb;
    spmm_half_kernel<<<grid_spmm, T>>>(bA, bB);   // layer 1: A -> B
    spmm_half_kernel<<<grid_spmm, T>>>(bB, bA);   // layer 2: B -> A (emb dead)

    // 6: layer 3 fused with batched dot (x1 = B, x2 = A)
    const int grid_dot = (BATCH + wpb - 1) / wpb;
    dot_fused_kernel<<<grid_dot, T>>>(users, items, emb_user, emb_item, out);
}

// round 15
// speedup vs baseline: 1.1514x; 1.1514x over previous
#include <cuda_runtime.h>
#include <cuda_fp16.h>
#include <stdint.h>

// ---------------- problem constants ----------------
#define N_USERS  50000
#define N_ITEMS  100000
#define N_NODES  (N_USERS + N_ITEMS)     // 150000
#define N_EDGES  2400000
#define DIM      64
#define BATCH    4096

#define TOTAL    (N_NODES * DIM)         // 9,600,000 floats
#define TOT8     (TOTAL / 8)             // uint4-of-half count per buffer

#define CAP      64                      // edge slots per node (Poisson(16): P(>64)~1e-20)

#define T           256
#define SCT_BLOCKS  (((N_EDGES / 4) + T - 1) / T)      // 2344
#define CVT_BLOCKS  ((TOT8 + T - 1) / T)               // 4688
#define AUX_BLOCKS  (((N_NODES / 4) + T - 1) / T)      // 147 (int4 copy/zero of cnt)

// ---------------- scratch (device globals; zero-initialized at load) ----------------
// TWO state buffers (fp16): bufA = emb -> layer-2 output; bufB = layer-1 output.
__device__ uint4 g_bufA[TOT8];
__device__ uint4 g_bufB[TOT8];

// direct-slotted edge buckets: node n owns g_edge[n*CAP .. n*CAP+deg)
__device__ int2  g_edge[(size_t)N_NODES * CAP];   // (src, val_fp32)
__device__ int   g_cnt [N_NODES];    // built by scatter; zeroed by spmm2's aux range
__device__ int   g_deg [N_NODES];    // stable degree copy (made during spmm1)

// ---------------- helpers ----------------
__device__ __forceinline__ unsigned pack_h2(float a, float b) {
    __half2 h = __floats2half2_rn(a, b);
    return *reinterpret_cast<unsigned*>(&h);
}
__device__ __forceinline__ float2 unpack_h2(unsigned u) {
    return __half22float2(*reinterpret_cast<__half2*>(&u));
}
__device__ __forceinline__ unsigned f32_to_h2(float f) {
    __half2 h = __float2half2_rn(f);
    return *reinterpret_cast<unsigned*>(&h);
}
__device__ __forceinline__ void hfma2_asm(unsigned& acc, unsigned v, unsigned h) {
    asm("fma.rn.f16x2 %0, %1, %2, %0;" : "+r"(acc) : "r"(v), "r"(h));
}

// ---------------- launch 1: direct scatter ∥ convert (disjoint block ranges) ------
// scatter: one pass, no rowptr needed. cnt is 0 on entry (zero-init / reset by
// the previous replay's spmm2 aux range).
__global__ void sct_cvt_kernel(const int* __restrict__ src,
                               const int* __restrict__ dst,
                               const float* __restrict__ vals,
                               const float* __restrict__ eu,
                               const float* __restrict__ ei) {
    if (blockIdx.x < SCT_BLOCKS) {
        int t = blockIdx.x * T + threadIdx.x;
        if (t * 4 >= N_EDGES) return;
        int4   s4 = reinterpret_cast<const int4*>(src)[t];
        int4   d4 = reinterpret_cast<const int4*>(dst)[t];
        float4 v4 = reinterpret_cast<const float4*>(vals)[t];
        int o;
        o = atomicAdd(&g_cnt[d4.x], 1);
        g_edge[(size_t)d4.x * CAP + o] = make_int2(s4.x, __float_as_int(v4.x));
        o = atomicAdd(&g_cnt[d4.y], 1);
        g_edge[(size_t)d4.y * CAP + o] = make_int2(s4.y, __float_as_int(v4.y));
        o = atomicAdd(&g_cnt[d4.z], 1);
        g_edge[(size_t)d4.z * CAP + o] = make_int2(s4.z, __float_as_int(v4.z));
        o = atomicAdd(&g_cnt[d4.w], 1);
        g_edge[(size_t)d4.w * CAP + o] = make_int2(s4.w, __float_as_int(v4.w));
    } else {
        int idx = (blockIdx.x - SCT_BLOCKS) * T + threadIdx.x;   // uint4 index
        if (idx >= TOT8) return;
        const int nu8 = (N_USERS * DIM) / 8;
        const float4* s;
        if (idx < nu8) s = reinterpret_cast<const float4*>(eu) + (size_t)idx * 2;
        else           s = reinterpret_cast<const float4*>(ei) + (size_t)(idx - nu8) * 2;
        float4 a = s[0], b = s[1];
        uint4 o;
        o.x = pack_h2(a.x, a.y);
        o.y = pack_h2(a.z, a.w);
        o.z = pack_h2(b.x, b.y);
        o.w = pack_h2(b.z, b.w);
        g_bufA[idx] = o;
    }
}

// ---------------- launches 2,3: gather SpMM (asm HFMA2) + aux range --------------
// one warp per dst node; c = lane&7 -> 16B chunk of row; slot = lane>>3 in [0,4)
// -> edge stream; 2-deep unroll keeps 2 independent gathers in flight per lane.
// deg_src: where to read degrees (cnt for layer 1, deg for layer 2).
// AUX blocks (beyond SPMM range): MODE 0 copies cnt->deg (layer 1; read-only on
// cnt, safe to co-run), MODE 1 zeroes cnt (layer 2; spmm2 reads deg only).
#define SPMM_BLOCKS ((N_NODES + 7) / 8)   // 18750 (8 warps per 256-thread block)

template<int MODE>
__global__ void __launch_bounds__(256, 8) spmm_half_kernel(
        const uint4* __restrict__ x, uint4* __restrict__ y,
        const int* __restrict__ deg_src) {
    if (blockIdx.x >= SPMM_BLOCKS) {
        int t = (blockIdx.x - SPMM_BLOCKS) * T + threadIdx.x;
        if (t < N_NODES / 4) {
            if (MODE == 0)
                reinterpret_cast<int4*>(g_deg)[t] =
                    reinterpret_cast<const int4*>(g_cnt)[t];
            else
                reinterpret_cast<int4*>(g_cnt)[t] = make_int4(0, 0, 0, 0);
        }
        return;
    }
    int node = blockIdx.x * 8 + (threadIdx.x >> 5);
    if (node >= N_NODES) return;
    int lane = threadIdx.x & 31;
    int c    = lane & 7;
    int slot = lane >> 3;

    int beg = node * CAP;
    int end = beg + deg_src[node];

    unsigned acc0 = 0u, acc1 = 0u, acc2 = 0u, acc3 = 0u;   // half2 +0.0 pairs

    int j = beg + slot;
    for (; j + 4 < end; j += 8) {
        int2  e0 = g_edge[j];
        int2  e1 = g_edge[j + 4];
        uint4 h0 = x[e0.x * 8 + c];
        uint4 h1 = x[e1.x * 8 + c];
        unsigned v0 = f32_to_h2(__int_as_float(e0.y));
        unsigned v1 = f32_to_h2(__int_as_float(e1.y));
        hfma2_asm(acc0, v0, h0.x);
        hfma2_asm(acc1, v0, h0.y);
        hfma2_asm(acc2, v0, h0.z);
        hfma2_asm(acc3, v0, h0.w);
        hfma2_asm(acc0, v1, h1.x);
        hfma2_asm(acc1, v1, h1.y);
        hfma2_asm(acc2, v1, h1.z);
        hfma2_asm(acc3, v1, h1.w);
    }
    if (j < end) {
        int2  e0 = g_edge[j];
        uint4 h0 = x[e0.x * 8 + c];
        unsigned v0 = f32_to_h2(__int_as_float(e0.y));
        hfma2_asm(acc0, v0, h0.x);
        hfma2_asm(acc1, v0, h0.y);
        hfma2_asm(acc2, v0, h0.z);
        hfma2_asm(acc3, v0, h0.w);
    }

    // convert to fp32 and combine the 4 slot groups in fp32
    float a[8];
    { float2 f = unpack_h2(acc0); a[0] = f.x; a[1] = f.y; }
    { float2 f = unpack_h2(acc1); a[2] = f.x; a[3] = f.y; }
    { float2 f = unpack_h2(acc2); a[4] = f.x; a[5] = f.y; }
    { float2 f = unpack_h2(acc3); a[6] = f.x; a[7] = f.y; }
    #pragma unroll
    for (int k = 0; k < 8; k++) {
        a[k] += __shfl_xor_sync(0xFFFFFFFFu, a[k], 8);
        a[k] += __shfl_xor_sync(0xFFFFFFFFu, a[k], 16);
    }
    if (slot == 0) {
        uint4 o;
        o.x = pack_h2(a[0], a[1]);
        o.y = pack_h2(a[2], a[3]);
        o.z = pack_h2(a[4], a[5]);
        o.w = pack_h2(a[6], a[7]);
        y[node * 8 + c] = o;
    }
}

// ---------------- launch 4: fused layer-3 gather + dot (fp32 accumulate) ---------
__device__ __forceinline__ void gather3_chunk(const uint4* __restrict__ x2,
                                              int node, int c, int slot,
                                              float (&g)[8]) {
    int beg = node * CAP;
    int end = beg + g_deg[node];
    #pragma unroll
    for (int k = 0; k < 8; k++) g[k] = 0.f;
    for (int j = beg + slot; j < end; j += 4) {
        int2  ed = g_edge[j];
        float v  = __int_as_float(ed.y);
        uint4 h  = x2[ed.x * 8 + c];
        float2 f;
        f = unpack_h2(h.x); g[0] += v * f.x; g[1] += v * f.y;
        f = unpack_h2(h.y); g[2] += v * f.x; g[3] += v * f.y;
        f = unpack_h2(h.z); g[4] += v * f.x; g[5] += v * f.y;
        f = unpack_h2(h.w); g[6] += v * f.x; g[7] += v * f.y;
    }
    #pragma unroll
    for (int k = 0; k < 8; k++) {
        g[k] += __shfl_xor_sync(0xFFFFFFFFu, g[k], 8);
        g[k] += __shfl_xor_sync(0xFFFFFFFFu, g[k], 16);
    }
}

// x1 = g_bufB (layer-1 output), x2 = g_bufA (layer-2 output)
__global__ void dot_fused_kernel(const int* __restrict__ users,
                                 const int* __restrict__ items,
                                 const float* __restrict__ eu,
                                 const float* __restrict__ ei,
                                 float* __restrict__ out) {
    int b = blockIdx.x * (blockDim.x >> 5) + (threadIdx.x >> 5);
    if (b >= BATCH) return;
    int lane = threadIdx.x & 31;
    int c    = lane & 7;
    int slot = lane >> 3;

    int u  = users[b];
    int im = items[b];
    int ni = N_USERS + im;

    float gu[8], gi[8];
    gather3_chunk(g_bufA, u,  c, slot, gu);
    gather3_chunk(g_bufA, ni, c, slot, gi);

    const float4* pu4 = reinterpret_cast<const float4*>(eu + u  * DIM + c * 8);
    const float4* pi4 = reinterpret_cast<const float4*>(ei + im * DIM + c * 8);
    float4 bu0 = pu4[0], bu1 = pu4[1];
    float4 bi0 = pi4[0], bi1 = pi4[1];

    uint4 u1h = g_bufB[u  * 8 + c], u2h = g_bufA[u  * 8 + c];
    uint4 i1h = g_bufB[ni * 8 + c], i2h = g_bufA[ni * 8 + c];

    float ru[8], ri[8];
    {
        float2 t;
        t = unpack_h2(u1h.x); ru[0] = bu0.x + t.x; ru[1] = bu0.y + t.y;
        t = unpack_h2(u1h.y); ru[2] = bu0.z + t.x; ru[3] = bu0.w + t.y;
        t = unpack_h2(u1h.z); ru[4] = bu1.x + t.x; ru[5] = bu1.y + t.y;
        t = unpack_h2(u1h.w); ru[6] = bu1.z + t.x; ru[7] = bu1.w + t.y;
        t = unpack_h2(u2h.x); ru[0] += t.x; ru[1] += t.y;
        t = unpack_h2(u2h.y); ru[2] += t.x; ru[3] += t.y;
        t = unpack_h2(u2h.z); ru[4] += t.x; ru[5] += t.y;
        t = unpack_h2(u2h.w); ru[6] += t.x; ru[7] += t.y;

        t = unpack_h2(i1h.x); ri[0] = bi0.x + t.x; ri[1] = bi0.y + t.y;
        t = unpack_h2(i1h.y); ri[2] = bi0.z + t.x; ri[3] = bi0.w + t.y;
        t = unpack_h2(i1h.z); ri[4] = bi1.x + t.x; ri[5] = bi1.y + t.y;
        t = unpack_h2(i1h.w); ri[6] = bi1.z + t.x; ri[7] = bi1.w + t.y;
        t = unpack_h2(i2h.x); ri[0] += t.x; ri[1] += t.y;
        t = unpack_h2(i2h.y); ri[2] += t.x; ri[3] += t.y;
        t = unpack_h2(i2h.z); ri[4] += t.x; ri[5] += t.y;
        t = unpack_h2(i2h.w); ri[6] += t.x; ri[7] += t.y;
    }

    float p = 0.f;
    #pragma unroll
    for (int k = 0; k < 8; k++)
        p += (ru[k] + gu[k]) * (ri[k] + gi[k]);

    p += __shfl_xor_sync(0xFFFFFFFFu, p, 1);
    p += __shfl_xor_sync(0xFFFFFFFFu, p, 2);
    p += __shfl_xor_sync(0xFFFFFFFFu, p, 4);

    if (lane == 0)
        out[b] = p * (1.0f / 16.0f);     // (1/4)^2 mean-pool factors
}

// ---------------- launch ----------------
extern "C" void kernel_launch(void* const* d_in, const int* in_sizes, int n_in,
                              void* d_out, int out_size) {
    (void)in_sizes; (void)n_in; (void)out_size;
    const float* emb_user = (const float*)d_in[0];
    const float* emb_item = (const float*)d_in[1];
    const float* vals     = (const float*)d_in[2];
    const int*   src      = (const int*)  d_in[3];
    const int*   dst      = (const int*)  d_in[4];
    const int*   users    = (const int*)  d_in[5];
    const int*   items    = (const int*)  d_in[6];
    float* out = (float*)d_out;

    uint4 *bA, *bB;
    int *cnt, *deg;
    cudaGetSymbolAddress((void**)&bA,  g_bufA);
    cudaGetSymbolAddress((void**)&bB,  g_bufB);
    cudaGetSymbolAddress((void**)&cnt, g_cnt);
    cudaGetSymbolAddress((void**)&deg, g_deg);

    // 1: direct scatter (builds cnt) ∥ convert emb -> fp16
    sct_cvt_kernel<<<SCT_BLOCKS + CVT_BLOCKS, T>>>(src, dst, vals,
                                                   emb_user, emb_item);

    // 2: spmm layer 1 (A -> B, degrees from cnt) ∥ copy cnt -> deg
    spmm_half_kernel<0><<<SPMM_BLOCKS + AUX_BLOCKS, T>>>(bA, bB, cnt);
    // 3: spmm layer 2 (B -> A, degrees from deg) ∥ zero cnt for next replay
    spmm_half_kernel<1><<<SPMM_BLOCKS + AUX_BLOCKS, T>>>(bB, bA, deg);

    // 4: layer 3 fused with batched dot (x1 = B, x2 = A; degrees from deg)
    const int wpb = T / 32;
    const int grid_dot = (BATCH + wpb - 1) / wpb;
    dot_fused_kernel<<<grid_dot, T>>>(users, items, emb_user, emb_item, out);
}

// round 16
// speedup vs baseline: 1.2195x; 1.0591x over previous
#include <cuda_runtime.h>
#include <cuda_fp16.h>
#include <stdint.h>

// ---------------- problem constants ----------------
#define N_USERS  50000
#define N_ITEMS  100000
#define N_NODES  (N_USERS + N_ITEMS)     // 150000
#define N_EDGES  2400000
#define DIM      64
#define BATCH    4096

#define TOTAL    (N_NODES * DIM)         // 9,600,000 floats
#define TOT8     (TOTAL / 8)             // uint4-of-half count per buffer

#define CAP      64                      // edge slots per node (Poisson(16): P(>64)~1e-20)

#define T           256
#define SCT_BLOCKS  (((N_EDGES / 4) + T - 1) / T)      // 2344
#define CVT_BLOCKS  ((TOT8 + T - 1) / T)               // 4688
#define AUX_BLOCKS  (((N_NODES / 4) + T - 1) / T)      // 147 (int4 copy/zero of cnt)

// ---------------- scratch (device globals; zero-initialized at load) ----------------
__device__ uint4 g_bufA[TOT8];           // emb -> layer-2 output (fp16)
__device__ uint4 g_bufB[TOT8];           // layer-1 output (fp16)

__device__ int2  g_edge[(size_t)N_NODES * CAP];   // (src, val_fp32), direct slots
__device__ int   g_cnt [N_NODES];    // built by scatter; zeroed by spmm2's aux range
__device__ int   g_deg [N_NODES];    // stable degree copy (made during spmm1)

// ---------------- helpers ----------------
__device__ __forceinline__ unsigned pack_h2(float a, float b) {
    __half2 h = __floats2half2_rn(a, b);
    return *reinterpret_cast<unsigned*>(&h);
}
__device__ __forceinline__ float2 unpack_h2(unsigned u) {
    return __half22float2(*reinterpret_cast<__half2*>(&u));
}
__device__ __forceinline__ unsigned f32_to_h2(float f) {
    __half2 h = __float2half2_rn(f);
    return *reinterpret_cast<unsigned*>(&h);
}
__device__ __forceinline__ void hfma2_asm(unsigned& acc, unsigned v, unsigned h) {
    asm("fma.rn.f16x2 %0, %1, %2, %0;" : "+r"(acc) : "r"(v), "r"(h));
}

// ---------------- launch 1: direct scatter ∥ convert (disjoint block ranges) ------
__global__ void sct_cvt_kernel(const int* __restrict__ src,
                               const int* __restrict__ dst,
                               const float* __restrict__ vals,
                               const float* __restrict__ eu,
                               const float* __restrict__ ei) {
    if (blockIdx.x < SCT_BLOCKS) {
        int t = blockIdx.x * T + threadIdx.x;
        if (t * 4 >= N_EDGES) return;
        int4   s4 = reinterpret_cast<const int4*>(src)[t];
        int4   d4 = reinterpret_cast<const int4*>(dst)[t];
        float4 v4 = reinterpret_cast<const float4*>(vals)[t];
        int o;
        o = atomicAdd(&g_cnt[d4.x], 1);
        g_edge[(size_t)d4.x * CAP + o] = make_int2(s4.x, __float_as_int(v4.x));
        o = atomicAdd(&g_cnt[d4.y], 1);
        g_edge[(size_t)d4.y * CAP + o] = make_int2(s4.y, __float_as_int(v4.y));
        o = atomicAdd(&g_cnt[d4.z], 1);
        g_edge[(size_t)d4.z * CAP + o] = make_int2(s4.z, __float_as_int(v4.z));
        o = atomicAdd(&g_cnt[d4.w], 1);
        g_edge[(size_t)d4.w * CAP + o] = make_int2(s4.w, __float_as_int(v4.w));
    } else {
        int idx = (blockIdx.x - SCT_BLOCKS) * T + threadIdx.x;   // uint4 index
        if (idx >= TOT8) return;
        const int nu8 = (N_USERS * DIM) / 8;
        const float4* s;
        if (idx < nu8) s = reinterpret_cast<const float4*>(eu) + (size_t)idx * 2;
        else           s = reinterpret_cast<const float4*>(ei) + (size_t)(idx - nu8) * 2;
        float4 a = s[0], b = s[1];
        uint4 o;
        o.x = pack_h2(a.x, a.y);
        o.y = pack_h2(a.z, a.w);
        o.z = pack_h2(b.x, b.y);
        o.w = pack_h2(b.z, b.w);
        g_bufA[idx] = o;
    }
}

// ---------------- launches 2,3: gather SpMM, 16 lanes per node -------------------
// 2 nodes per warp. Within a node-half: c = lane&7 -> 16B chunk of the 128B row;
// slot = (lane>>3)&1 in [0,2) -> edge stream (stride 2, 2-deep unroll).
// Reduction: ONE xor-8 level (serves both nodes in the warp).
// AUX blocks: MODE 0 copies cnt->deg (layer 1), MODE 1 zeroes cnt (layer 2).
#define SPMM_BLOCKS ((N_NODES + 15) / 16)   // 9375 (16 nodes per 256-thread block)

template<int MODE>
__global__ void __launch_bounds__(256, 8) spmm_half_kernel(
        const uint4* __restrict__ x, uint4* __restrict__ y,
        const int* __restrict__ deg_src) {
    if (blockIdx.x >= SPMM_BLOCKS) {
        int t = (blockIdx.x - SPMM_BLOCKS) * T + threadIdx.x;
        if (t < N_NODES / 4) {
            if (MODE == 0)
                reinterpret_cast<int4*>(g_deg)[t] =
                    reinterpret_cast<const int4*>(g_cnt)[t];
            else
                reinterpret_cast<int4*>(g_cnt)[t] = make_int4(0, 0, 0, 0);
        }
        return;
    }
    int node = blockIdx.x * 16 + (threadIdx.x >> 4);
    if (node >= N_NODES) return;
    int l16  = threadIdx.x & 15;
    int c    = l16 & 7;
    int slot = l16 >> 3;          // 0 or 1

    int beg = node * CAP;
    int end = beg + deg_src[node];

    unsigned acc0 = 0u, acc1 = 0u, acc2 = 0u, acc3 = 0u;   // half2 +0.0 pairs

    int j = beg + slot;
    for (; j + 2 < end; j += 4) {
        int2  e0 = g_edge[j];
        int2  e1 = g_edge[j + 2];
        uint4 h0 = x[e0.x * 8 + c];
        uint4 h1 = x[e1.x * 8 + c];
        unsigned v0 = f32_to_h2(__int_as_float(e0.y));
        unsigned v1 = f32_to_h2(__int_as_float(e1.y));
        hfma2_asm(acc0, v0, h0.x);
        hfma2_asm(acc1, v0, h0.y);
        hfma2_asm(acc2, v0, h0.z);
        hfma2_asm(acc3, v0, h0.w);
        hfma2_asm(acc0, v1, h1.x);
        hfma2_asm(acc1, v1, h1.y);
        hfma2_asm(acc2, v1, h1.z);
        hfma2_asm(acc3, v1, h1.w);
    }
    if (j < end) {
        int2  e0 = g_edge[j];
        uint4 h0 = x[e0.x * 8 + c];
        unsigned v0 = f32_to_h2(__int_as_float(e0.y));
        hfma2_asm(acc0, v0, h0.x);
        hfma2_asm(acc1, v0, h0.y);
        hfma2_asm(acc2, v0, h0.z);
        hfma2_asm(acc3, v0, h0.w);
    }

    // convert to fp32; combine the 2 slot groups (xor 8 stays within node-half)
    float a[8];
    { float2 f = unpack_h2(acc0); a[0] = f.x; a[1] = f.y; }
    { float2 f = unpack_h2(acc1); a[2] = f.x; a[3] = f.y; }
    { float2 f = unpack_h2(acc2); a[4] = f.x; a[5] = f.y; }
    { float2 f = unpack_h2(acc3); a[6] = f.x; a[7] = f.y; }
    #pragma unroll
    for (int k = 0; k < 8; k++)
        a[k] += __shfl_xor_sync(0xFFFFFFFFu, a[k], 8);
    if (slot == 0) {
        uint4 o;
        o.x = pack_h2(a[0], a[1]);
        o.y = pack_h2(a[2], a[3]);
        o.z = pack_h2(a[4], a[5]);
        o.w = pack_h2(a[6], a[7]);
        y[node * 8 + c] = o;
    }
}

// ---------------- launch 4: fused layer-3 gather + dot, warp per (b, side) -------
// 256-thread block = 8 warps = 4 batch elements; warp w: b_local = w>>1,
// side = w&1 (0 = user, 1 = item). Each warp does ONE gather + base sum; item
// side publishes its r-vector via smem; user side computes the dot.
__global__ void dot_fused_kernel(const int* __restrict__ users,
                                 const int* __restrict__ items,
                                 const float* __restrict__ eu,
                                 const float* __restrict__ ei,
                                 float* __restrict__ out) {
    __shared__ float s_ri[4][64];

    int w    = threadIdx.x >> 5;
    int bl   = w >> 1;                    // 0..3
    int side = w & 1;                     // 0 user, 1 item
    int b = blockIdx.x * 4 + bl;
    if (b >= BATCH) return;
    int lane = threadIdx.x & 31;
    int c    = lane & 7;
    int slot = lane >> 3;                 // 0..3

    int node, im = 0;
    if (side == 0) node = users[b];
    else { im = items[b]; node = N_USERS + im; }

    // layer-3 gather from x2 (= g_bufA), fp32 accumulate, 4 slots
    float g[8];
    #pragma unroll
    for (int k = 0; k < 8; k++) g[k] = 0.f;
    {
        int beg = node * CAP;
        int end = beg + g_deg[node];
        for (int j = beg + slot; j < end; j += 4) {
            int2  ed = g_edge[j];
            float v  = __int_as_float(ed.y);
            uint4 h  = g_bufA[ed.x * 8 + c];
            float2 f;
            f = unpack_h2(h.x); g[0] += v * f.x; g[1] += v * f.y;
            f = unpack_h2(h.y); g[2] += v * f.x; g[3] += v * f.y;
            f = unpack_h2(h.z); g[4] += v * f.x; g[5] += v * f.y;
            f = unpack_h2(h.w); g[6] += v * f.x; g[7] += v * f.y;
        }
        #pragma unroll
        for (int k = 0; k < 8; k++) {
            g[k] += __shfl_xor_sync(0xFFFFFFFFu, g[k], 8);
            g[k] += __shfl_xor_sync(0xFFFFFFFFu, g[k], 16);
        }
    }

    // base terms: emb (fp32 input) + x1 (bufB) + x2 (bufA)
    const float* ebase = (side == 0) ? eu + node * DIM : ei + im * DIM;
    const float4* p4 = reinterpret_cast<const float4*>(ebase + c * 8);
    float4 b0 = p4[0], b1 = p4[1];
    uint4 h1v = g_bufB[node * 8 + c];
    uint4 h2v = g_bufA[node * 8 + c];

    float r[8];
    {
        float2 t;
        t = unpack_h2(h1v.x); r[0] = b0.x + t.x; r[1] = b0.y + t.y;
        t = unpack_h2(h1v.y); r[2] = b0.z + t.x; r[3] = b0.w + t.y;
        t = unpack_h2(h1v.z); r[4] = b1.x + t.x; r[5] = b1.y + t.y;
        t = unpack_h2(h1v.w); r[6] = b1.z + t.x; r[7] = b1.w + t.y;
        t = unpack_h2(h2v.x); r[0] += t.x; r[1] += t.y;
        t = unpack_h2(h2v.y); r[2] += t.x; r[3] += t.y;
        t = unpack_h2(h2v.z); r[4] += t.x; r[5] += t.y;
        t = unpack_h2(h2v.w); r[6] += t.x; r[7] += t.y;
        #pragma unroll
        for (int k = 0; k < 8; k++) r[k] += g[k];
    }

    // item side publishes its r-vector
    if (side == 1 && slot == 0) {
        #pragma unroll
        for (int k = 0; k < 8; k++) s_ri[bl][c * 8 + k] = r[k];
    }
    __syncthreads();

    // user side computes the dot
    if (side == 0) {
        float p = 0.f;
        #pragma unroll
        for (int k = 0; k < 8; k++) p += r[k] * s_ri[bl][c * 8 + k];
        // p replicated across the 4 slot groups; reduce over the 8 c-lanes
        p += __shfl_xor_sync(0xFFFFFFFFu, p, 1);
        p += __shfl_xor_sync(0xFFFFFFFFu, p, 2);
        p += __shfl_xor_sync(0xFFFFFFFFu, p, 4);
        if (lane == 0)
            out[b] = p * (1.0f / 16.0f);     // (1/4)^2 mean-pool factors
    }
}

// ---------------- launch ----------------
extern "C" void kernel_launch(void* const* d_in, const int* in_sizes, int n_in,
                              void* d_out, int out_size) {
    (void)in_sizes; (void)n_in; (void)out_size;
    const float* emb_user = (const float*)d_in[0];
    const float* emb_item = (const float*)d_in[1];
    const float* vals     = (const float*)d_in[2];
    const int*   src      = (const int*)  d_in[3];
    const int*   dst      = (const int*)  d_in[4];
    const int*   users    = (const int*)  d_in[5];
    const int*   items    = (const int*)  d_in[6];
    float* out = (float*)d_out;

    uint4 *bA, *bB;
    int *cnt, *deg;
    cudaGetSymbolAddress((void**)&bA,  g_bufA);
    cudaGetSymbolAddress((void**)&bB,  g_bufB);
    cudaGetSymbolAddress((void**)&cnt, g_cnt);
    cudaGetSymbolAddress((void**)&deg, g_deg);

    // 1: direct scatter (builds cnt) ∥ convert emb -> fp16
    sct_cvt_kernel<<<SCT_BLOCKS + CVT_BLOCKS, T>>>(src, dst, vals,
                                                   emb_user, emb_item);

    // 2: spmm layer 1 (A -> B, degrees from cnt) ∥ copy cnt -> deg
    spmm_half_kernel<0><<<SPMM_BLOCKS + AUX_BLOCKS, T>>>(bA, bB, cnt);
    // 3: spmm layer 2 (B -> A, degrees from deg) ∥ zero cnt for next replay
    spmm_half_kernel<1><<<SPMM_BLOCKS + AUX_BLOCKS, T>>>(bB, bA, deg);

    // 4: layer 3 fused with batched dot (x1 = B, x2 = A; degrees from deg)
    const int grid_dot = (BATCH + 3) / 4;
    dot_fused_kernel<<<grid_dot, T>>>(users, items, emb_user, emb_item, out);
}

// round 17
// speedup vs baseline: 1.2348x; 1.0126x over previous
#include <cuda_runtime.h>
#include <cuda_fp16.h>
#include <stdint.h>

// ---------------- problem constants ----------------
#define N_USERS  50000
#define N_ITEMS  100000
#define N_NODES  (N_USERS + N_ITEMS)     // 150000
#define N_EDGES  2400000
#define DIM      64
#define BATCH    4096

#define TOTAL    (N_NODES * DIM)         // 9,600,000 floats
#define TOT8     (TOTAL / 8)             // uint4-of-half count per buffer

#define CAP      64                      // edge slots per node (Poisson(16): P(>64)~1e-20)

#define T           256
#define SCT_BLOCKS  (((N_EDGES / 4) + T - 1) / T)      // 2344
#define CVT_BLOCKS  ((TOT8 + T - 1) / T)               // 4688
#define AUX_BLOCKS  (((N_NODES / 4) + T - 1) / T)      // 147 (int4 copy/zero of cnt)

// ---------------- scratch (device globals; zero-initialized at load) ----------------
__device__ uint4 g_bufA[TOT8];           // emb -> layer-2 output (fp16)
__device__ uint4 g_bufB[TOT8];           // layer-1 output (fp16)

__device__ int2  g_edge[(size_t)N_NODES * CAP];   // (src, val_fp32), direct slots
__device__ int   g_cnt [N_NODES];    // built by scatter; zeroed by spmm2's aux range
__device__ int   g_deg [N_NODES];    // stable degree copy (made during spmm1)

// ---------------- helpers ----------------
__device__ __forceinline__ unsigned pack_h2(float a, float b) {
    __half2 h = __floats2half2_rn(a, b);
    return *reinterpret_cast<unsigned*>(&h);
}
__device__ __forceinline__ float2 unpack_h2(unsigned u) {
    return __half22float2(*reinterpret_cast<__half2*>(&u));
}
__device__ __forceinline__ unsigned f32_to_h2(float f) {
    __half2 h = __float2half2_rn(f);
    return *reinterpret_cast<unsigned*>(&h);
}
__device__ __forceinline__ void hfma2_asm(unsigned& acc, unsigned v, unsigned h) {
    asm("fma.rn.f16x2 %0, %1, %2, %0;" : "+r"(acc) : "r"(v), "r"(h));
}

// ---------------- launch 1: direct scatter ∥ convert (disjoint block ranges) ------
__global__ void sct_cvt_kernel(const int* __restrict__ src,
                               const int* __restrict__ dst,
                               const float* __restrict__ vals,
                               const float* __restrict__ eu,
                               const float* __restrict__ ei) {
    if (blockIdx.x < SCT_BLOCKS) {
        int t = blockIdx.x * T + threadIdx.x;
        if (t * 4 >= N_EDGES) return;
        int4   s4 = reinterpret_cast<const int4*>(src)[t];
        int4   d4 = reinterpret_cast<const int4*>(dst)[t];
        float4 v4 = reinterpret_cast<const float4*>(vals)[t];
        int o;
        o = atomicAdd(&g_cnt[d4.x], 1);
        g_edge[(size_t)d4.x * CAP + o] = make_int2(s4.x, __float_as_int(v4.x));
        o = atomicAdd(&g_cnt[d4.y], 1);
        g_edge[(size_t)d4.y * CAP + o] = make_int2(s4.y, __float_as_int(v4.y));
        o = atomicAdd(&g_cnt[d4.z], 1);
        g_edge[(size_t)d4.z * CAP + o] = make_int2(s4.z, __float_as_int(v4.z));
        o = atomicAdd(&g_cnt[d4.w], 1);
        g_edge[(size_t)d4.w * CAP + o] = make_int2(s4.w, __float_as_int(v4.w));
    } else {
        int idx = (blockIdx.x - SCT_BLOCKS) * T + threadIdx.x;   // uint4 index
        if (idx >= TOT8) return;
        const int nu8 = (N_USERS * DIM) / 8;
        const float4* s;
        if (idx < nu8) s = reinterpret_cast<const float4*>(eu) + (size_t)idx * 2;
        else           s = reinterpret_cast<const float4*>(ei) + (size_t)(idx - nu8) * 2;
        float4 a = s[0], b = s[1];
        uint4 o;
        o.x = pack_h2(a.x, a.y);
        o.y = pack_h2(a.z, a.w);
        o.z = pack_h2(b.x, b.y);
        o.w = pack_h2(b.z, b.w);
        g_bufA[idx] = o;
    }
}

// ---------------- launches 2,3: gather SpMM, 16 lanes per node -------------------
// 2 nodes per warp. Within a node-half: c = lane&7 -> 16B chunk of the 128B row;
// slot = (lane>>3)&1 in [0,2) -> edge stream (stride 2, 2-deep unroll).
// Reduction: ONE xor-8 level (serves both nodes in the warp).
// AUX blocks: MODE 0 copies cnt->deg (layer 1), MODE 1 zeroes cnt (layer 2).
#define SPMM_BLOCKS ((N_NODES + 15) / 16)   // 9375 (16 nodes per 256-thread block)

template<int MODE>
__global__ void __launch_bounds__(256, 8) spmm_half_kernel(
        const uint4* __restrict__ x, uint4* __restrict__ y,
        const int* __restrict__ deg_src) {
    if (blockIdx.x >= SPMM_BLOCKS) {
        int t = (blockIdx.x - SPMM_BLOCKS) * T + threadIdx.x;
        if (t < N_NODES / 4) {
            if (MODE == 0)
                reinterpret_cast<int4*>(g_deg)[t] =
                    reinterpret_cast<const int4*>(g_cnt)[t];
            else
                reinterpret_cast<int4*>(g_cnt)[t] = make_int4(0, 0, 0, 0);
        }
        return;
    }
    int node = blockIdx.x * 16 + (threadIdx.x >> 4);
    if (node >= N_NODES) return;
    int l16  = threadIdx.x & 15;
    int c    = l16 & 7;
    int slot = l16 >> 3;          // 0 or 1

    int beg = node * CAP;
    int end = beg + deg_src[node];

    unsigned acc0 = 0u, acc1 = 0u, acc2 = 0u, acc3 = 0u;   // half2 +0.0 pairs

    int j = beg + slot;
    for (; j + 2 < end; j += 4) {
        int2  e0 = g_edge[j];
        int2  e1 = g_edge[j + 2];
        uint4 h0 = x[e0.x * 8 + c];
        uint4 h1 = x[e1.x * 8 + c];
        unsigned v0 = f32_to_h2(__int_as_float(e0.y));
        unsigned v1 = f32_to_h2(__int_as_float(e1.y));
        hfma2_asm(acc0, v0, h0.x);
        hfma2_asm(acc1, v0, h0.y);
        hfma2_asm(acc2, v0, h0.z);
        hfma2_asm(acc3, v0, h0.w);
        hfma2_asm(acc0, v1, h1.x);
        hfma2_asm(acc1, v1, h1.y);
        hfma2_asm(acc2, v1, h1.z);
        hfma2_asm(acc3, v1, h1.w);
    }
    if (j < end) {
        int2  e0 = g_edge[j];
        uint4 h0 = x[e0.x * 8 + c];
        unsigned v0 = f32_to_h2(__int_as_float(e0.y));
        hfma2_asm(acc0, v0, h0.x);
        hfma2_asm(acc1, v0, h0.y);
        hfma2_asm(acc2, v0, h0.z);
        hfma2_asm(acc3, v0, h0.w);
    }

    // convert to fp32; combine the 2 slot groups (xor 8 stays within node-half)
    float a[8];
    { float2 f = unpack_h2(acc0); a[0] = f.x; a[1] = f.y; }
    { float2 f = unpack_h2(acc1); a[2] = f.x; a[3] = f.y; }
    { float2 f = unpack_h2(acc2); a[4] = f.x; a[5] = f.y; }
    { float2 f = unpack_h2(acc3); a[6] = f.x; a[7] = f.y; }
    #pragma unroll
    for (int k = 0; k < 8; k++)
        a[k] += __shfl_xor_sync(0xFFFFFFFFu, a[k], 8);
    if (slot == 0) {
        uint4 o;
        o.x = pack_h2(a[0], a[1]);
        o.y = pack_h2(a[2], a[3]);
        o.z = pack_h2(a[4], a[5]);
        o.w = pack_h2(a[6], a[7]);
        y[node * 8 + c] = o;
    }
}

// ---------------- launch 4: fused layer-3 gather + dot, split-warp sides ---------
// one warp per batch element: lanes 0-15 process the USER node, lanes 16-31 the
// ITEM node (per half: c = lane&7, slot = (lane>>3)&1). No smem, no barrier —
// sides combine via one xor-16 shuffle per chunk register.
__global__ void dot_fused_kernel(const int* __restrict__ users,
                                 const int* __restrict__ items,
                                 const float* __restrict__ eu,
                                 const float* __restrict__ ei,
                                 float* __restrict__ out) {
    int b = blockIdx.x * (blockDim.x >> 5) + (threadIdx.x >> 5);
    if (b >= BATCH) return;
    int lane = threadIdx.x & 31;
    int side = lane >> 4;                 // 0 user, 1 item
    int c    = lane & 7;
    int slot = (lane >> 3) & 1;           // 0 or 1

    int node, im = 0;
    if (side == 0) node = users[b];
    else { im = items[b]; node = N_USERS + im; }

    // layer-3 gather from x2 (= g_bufA), fp32 accumulate, 2 slots per side
    float g[8];
    #pragma unroll
    for (int k = 0; k < 8; k++) g[k] = 0.f;
    {
        int beg = node * CAP;
        int end = beg + g_deg[node];
        int j = beg + slot;
        for (; j + 2 < end; j += 4) {
            int2  e0 = g_edge[j];
            int2  e1 = g_edge[j + 2];
            float v0 = __int_as_float(e0.y);
            float v1 = __int_as_float(e1.y);
            uint4 h0 = g_bufA[e0.x * 8 + c];
            uint4 h1 = g_bufA[e1.x * 8 + c];
            float2 f;
            f = unpack_h2(h0.x); g[0] += v0 * f.x; g[1] += v0 * f.y;
            f = unpack_h2(h0.y); g[2] += v0 * f.x; g[3] += v0 * f.y;
            f = unpack_h2(h0.z); g[4] += v0 * f.x; g[5] += v0 * f.y;
            f = unpack_h2(h0.w); g[6] += v0 * f.x; g[7] += v0 * f.y;
            f = unpack_h2(h1.x); g[0] += v1 * f.x; g[1] += v1 * f.y;
            f = unpack_h2(h1.y); g[2] += v1 * f.x; g[3] += v1 * f.y;
            f = unpack_h2(h1.z); g[4] += v1 * f.x; g[5] += v1 * f.y;
            f = unpack_h2(h1.w); g[6] += v1 * f.x; g[7] += v1 * f.y;
        }
        if (j < end) {
            int2  e0 = g_edge[j];
            float v0 = __int_as_float(e0.y);
            uint4 h0 = g_bufA[e0.x * 8 + c];
            float2 f;
            f = unpack_h2(h0.x); g[0] += v0 * f.x; g[1] += v0 * f.y;
            f = unpack_h2(h0.y); g[2] += v0 * f.x; g[3] += v0 * f.y;
            f = unpack_h2(h0.z); g[4] += v0 * f.x; g[5] += v0 * f.y;
            f = unpack_h2(h0.w); g[6] += v0 * f.x; g[7] += v0 * f.y;
        }
        // combine the 2 slot groups within the side (xor 8 stays in the half)
        #pragma unroll
        for (int k = 0; k < 8; k++)
            g[k] += __shfl_xor_sync(0xFFFFFFFFu, g[k], 8);
    }

    // base terms: emb (fp32 input) + x1 (bufB) + x2 (bufA)
    const float* ebase = (side == 0) ? eu + node * DIM : ei + im * DIM;
    const float4* p4 = reinterpret_cast<const float4*>(ebase + c * 8);
    float4 b0 = p4[0], b1 = p4[1];
    uint4 h1v = g_bufB[node * 8 + c];
    uint4 h2v = g_bufA[node * 8 + c];

    float r[8];
    {
        float2 t;
        t = unpack_h2(h1v.x); r[0] = b0.x + t.x; r[1] = b0.y + t.y;
        t = unpack_h2(h1v.y); r[2] = b0.z + t.x; r[3] = b0.w + t.y;
        t = unpack_h2(h1v.z); r[4] = b1.x + t.x; r[5] = b1.y + t.y;
        t = unpack_h2(h1v.w); r[6] = b1.z + t.x; r[7] = b1.w + t.y;
        t = unpack_h2(h2v.x); r[0] += t.x; r[1] += t.y;
        t = unpack_h2(h2v.y); r[2] += t.x; r[3] += t.y;
        t = unpack_h2(h2v.z); r[4] += t.x; r[5] += t.y;
        t = unpack_h2(h2v.w); r[6] += t.x; r[7] += t.y;
        #pragma unroll
        for (int k = 0; k < 8; k++) r[k] += g[k];
    }

    // cross-side product: lane l (user half) pairs with lane l+16 (item half)
    float p = 0.f;
    #pragma unroll
    for (int k = 0; k < 8; k++) {
        float other = __shfl_xor_sync(0xFFFFFFFFu, r[k], 16);
        p += r[k] * other;
    }
    // p on user-half lanes = desired products; reduce over 8 c-lanes (p is
    // slot-replicated after the xor-8 above... both slots hold identical r,
    // so reduce over c only)
    p += __shfl_xor_sync(0xFFFFFFFFu, p, 1);
    p += __shfl_xor_sync(0xFFFFFFFFu, p, 2);
    p += __shfl_xor_sync(0xFFFFFFFFu, p, 4);

    if (lane == 0)
        out[b] = p * (1.0f / 16.0f);     // (1/4)^2 mean-pool factors
}

// ---------------- launch ----------------
extern "C" void kernel_launch(void* const* d_in, const int* in_sizes, int n_in,
                              void* d_out, int out_size) {
    (void)in_sizes; (void)n_in; (void)out_size;
    const float* emb_user = (const float*)d_in[0];
    const float* emb_item = (const float*)d_in[1];
    const float* vals     = (const float*)d_in[2];
    const int*   src      = (const int*)  d_in[3];
    const int*   dst      = (const int*)  d_in[4];
    const int*   users    = (const int*)  d_in[5];
    const int*   items    = (const int*)  d_in[6];
    float* out = (float*)d_out;

    uint4 *bA, *bB;
    int *cnt, *deg;
    cudaGetSymbolAddress((void**)&bA,  g_bufA);
    cudaGetSymbolAddress((void**)&bB,  g_bufB);
    cudaGetSymbolAddress((void**)&cnt, g_cnt);
    cudaGetSymbolAddress((void**)&deg, g_deg);

    // 1: direct scatter (builds cnt) ∥ convert emb -> fp16
    sct_cvt_kernel<<<SCT_BLOCKS + CVT_BLOCKS, T>>>(src, dst, vals,
                                                   emb_user, emb_item);

    // 2: spmm layer 1 (A -> B, degrees from cnt) ∥ copy cnt -> deg
    spmm_half_kernel<0><<<SPMM_BLOCKS + AUX_BLOCKS, T>>>(bA, bB, cnt);
    // 3: spmm layer 2 (B -> A, degrees from deg) ∥ zero cnt for next replay
    spmm_half_kernel<1><<<SPMM_BLOCKS + AUX_BLOCKS, T>>>(bB, bA, deg);

    // 4: layer 3 fused with batched dot (x1 = B, x2 = A; degrees from deg)
    const int wpb = T / 32;
    const int grid_dot = (BATCH + wpb - 1) / wpb;
    dot_fused_kernel<<<grid_dot, T>>>(users, items, emb_user, emb_item, out);
}